// round 7
// baseline (speedup 1.0000x reference)
#include <cuda_runtime.h>
#include <cstdint>
#include <math.h>

#define HDIM 128
#define MAXN 200000

// ---------------- device scratch ----------------
__device__ float g_mh1[MAXN * HDIM];
__device__ float g_mc1[MAXN * HDIM];
__device__ float g_mh2[MAXN * HDIM];
__device__ float g_mc2[MAXN * HDIM];
// transposed + tf32-rounded weights: [phase][n=512][k=256]
__device__ uint32_t g_Bt[2 * 512 * 256];

__device__ __forceinline__ uint32_t smem_u32(const void* p) {
    uint32_t a;
    asm("{ .reg .u64 t; cvta.to.shared.u64 t, %1; cvt.u32.u64 %0, t; }" : "=r"(a) : "l"(p));
    return a;
}
__device__ __forceinline__ uint32_t f2tf32(float f) {
    uint32_t o;
    asm("cvt.rna.tf32.f32 %0, %1;" : "=r"(o) : "f"(f));
    return o;
}
__device__ __forceinline__ void cp_async16(uint32_t dst, const void* src, int src_bytes) {
    asm volatile("cp.async.cg.shared.global [%0], [%1], 16, %2;"
                 :: "r"(dst), "l"(src), "r"(src_bytes) : "memory");
}
__device__ __forceinline__ void cp_commit() {
    asm volatile("cp.async.commit_group;" ::: "memory");
}
__device__ __forceinline__ void cp_wait1() {
    asm volatile("cp.async.wait_group 1;" ::: "memory");
}
__device__ __forceinline__ void cp_wait0() {
    asm volatile("cp.async.wait_group 0;" ::: "memory");
}
__device__ __forceinline__ void mma_tf32(float* d, uint32_t a0, uint32_t a1, uint32_t a2,
                                         uint32_t a3, uint32_t b0, uint32_t b1) {
    asm volatile(
        "mma.sync.aligned.m16n8k8.row.col.f32.tf32.tf32.f32 "
        "{%0,%1,%2,%3}, {%4,%5,%6,%7}, {%8,%9}, {%0,%1,%2,%3};"
        : "+f"(d[0]), "+f"(d[1]), "+f"(d[2]), "+f"(d[3])
        : "r"(a0), "r"(a1), "r"(a2), "r"(a3), "r"(b0), "r"(b1));
}

// XOR-swizzled smem offset for 128x32-float tiles (float index)
__device__ __forceinline__ int soff(int r, int kk) {
    return r * 32 + (((kk >> 2) ^ (r & 7)) << 2) + (kk & 3);
}

// ---------------- gather: sorted-dst segment sum, 1 warp / node, 4-edge MLP (R5 best) ----------------
__global__ void gather_kernel(const float* __restrict__ h1, const float* __restrict__ c1,
                              const float* __restrict__ h2, const float* __restrict__ c2,
                              const int* __restrict__ src, const int* __restrict__ dst,
                              int n, int e)
{
    int node = (blockIdx.x * blockDim.x + threadIdx.x) >> 5;
    int lane = threadIdx.x & 31;
    if (node >= n) return;

    int lo = 0, hi = e;
    while (lo < hi) { int mid = (lo + hi) >> 1; if (dst[mid] < node) lo = mid + 1; else hi = mid; }
    int s = lo;
    hi = e;
    while (lo < hi) { int mid = (lo + hi) >> 1; if (dst[mid] < node + 1) lo = mid + 1; else hi = mid; }
    int send = lo;

    float4 a1 = make_float4(0.f, 0.f, 0.f, 0.f);
    float4 a2 = a1, a3 = a1, a4 = a1;
    const int col = lane * 4;

    int idx = s;
    for (; idx + 4 <= send; idx += 4) {
        int b0 = src[idx + 0] * HDIM + col;
        int b1 = src[idx + 1] * HDIM + col;
        int b2 = src[idx + 2] * HDIM + col;
        int b3 = src[idx + 3] * HDIM + col;
        float4 h1a = *(const float4*)(h1 + b0), h1b = *(const float4*)(h1 + b1);
        float4 h1c = *(const float4*)(h1 + b2), h1d = *(const float4*)(h1 + b3);
        float4 c1a = *(const float4*)(c1 + b0), c1b = *(const float4*)(c1 + b1);
        float4 c1c = *(const float4*)(c1 + b2), c1d = *(const float4*)(c1 + b3);
        float4 h2a = *(const float4*)(h2 + b0), h2b = *(const float4*)(h2 + b1);
        float4 h2c = *(const float4*)(h2 + b2), h2d = *(const float4*)(h2 + b3);
        float4 c2a = *(const float4*)(c2 + b0), c2b = *(const float4*)(c2 + b1);
        float4 c2c = *(const float4*)(c2 + b2), c2d = *(const float4*)(c2 + b3);
        a1.x += (h1a.x + h1b.x) + (h1c.x + h1d.x);
        a1.y += (h1a.y + h1b.y) + (h1c.y + h1d.y);
        a1.z += (h1a.z + h1b.z) + (h1c.z + h1d.z);
        a1.w += (h1a.w + h1b.w) + (h1c.w + h1d.w);
        a2.x += (c1a.x + c1b.x) + (c1c.x + c1d.x);
        a2.y += (c1a.y + c1b.y) + (c1c.y + c1d.y);
        a2.z += (c1a.z + c1b.z) + (c1c.z + c1d.z);
        a2.w += (c1a.w + c1b.w) + (c1c.w + c1d.w);
        a3.x += (h2a.x + h2b.x) + (h2c.x + h2d.x);
        a3.y += (h2a.y + h2b.y) + (h2c.y + h2d.y);
        a3.z += (h2a.z + h2b.z) + (h2c.z + h2d.z);
        a3.w += (h2a.w + h2b.w) + (h2c.w + h2d.w);
        a4.x += (c2a.x + c2b.x) + (c2c.x + c2d.x);
        a4.y += (c2a.y + c2b.y) + (c2c.y + c2d.y);
        a4.z += (c2a.z + c2b.z) + (c2c.z + c2d.z);
        a4.w += (c2a.w + c2b.w) + (c2c.w + c2d.w);
    }
    for (; idx < send; ++idx) {
        int b = src[idx] * HDIM + col;
        float4 v;
        v = *(const float4*)(h1 + b); a1.x += v.x; a1.y += v.y; a1.z += v.z; a1.w += v.w;
        v = *(const float4*)(c1 + b); a2.x += v.x; a2.y += v.y; a2.z += v.z; a2.w += v.w;
        v = *(const float4*)(h2 + b); a3.x += v.x; a3.y += v.y; a3.z += v.z; a3.w += v.w;
        v = *(const float4*)(c2 + b); a4.x += v.x; a4.y += v.y; a4.z += v.z; a4.w += v.w;
    }

    int ob = node * HDIM + col;
    *(float4*)(g_mh1 + ob) = a1;
    *(float4*)(g_mc1 + ob) = a2;
    *(float4*)(g_mh2 + ob) = a3;
    *(float4*)(g_mc2 + ob) = a4;
}

// ---------------- prep: weights -> [n=512][k=256] (B^T), tf32-rounded ----------------
__global__ void prep_kernel(const float* __restrict__ W1, const float* __restrict__ U1,
                            const float* __restrict__ W2, const float* __restrict__ U2)
{
    int p = blockIdx.y;
    int i = blockIdx.x * 256 + threadIdx.x;
    int k = i >> 9, n = i & 511;
    const float* W = p ? W2 : W1;
    const float* U = p ? U2 : U1;
    float v = (k < 128) ? W[k * 512 + n] : U[(k - 128) * 512 + n];
    g_Bt[p * 131072 + n * 256 + k] = f2tf32(v);
}

// ---------------- fused HMMA(tf32) GEMM + gates ----------------
// 128x128 block tile, K=256, BK=32, 512 threads, 16 warps of 32x32 warp tiles.
// acc = 32 regs/thread -> fits launch_bounds(512, 2) = 64-reg cap, 32 warps/SM.
#define S_A0 0
#define S_A1 16384
#define S_B0 32768
#define S_B1 49152
#define ES_STRIDE 132
#define SMEM_TOTAL (128 * ES_STRIDE * 4)   // 67584

__global__ __launch_bounds__(512, 2)
void lstm_mma_kernel(const float* __restrict__ A1,
                     const float* __restrict__ bW, const float* __restrict__ bU,
                     float* __restrict__ h_out, float* __restrict__ c_out,
                     int nrows, int phase)
{
    extern __shared__ char smem[];
    const uint32_t sbase = smem_u32(smem);
    uint32_t* Sf = (uint32_t*)smem;
    const int tid = threadIdx.x;
    const int h0   = blockIdx.x * 32;
    const int row0 = blockIdx.y * 128;

    const float* A2 = phase ? g_mh2 : g_mh1;
    const float* mc = phase ? g_mc2 : g_mc1;
    const uint32_t* Bt = g_Bt + phase * 131072;

    // ---- loop-invariant staging state (512 threads: 2 float4 each for A and B) ----
    const int r0 = tid >> 3;               // 0..63
    const int q  = tid & 7;
    const uint32_t sw0 = (uint32_t)(r0 * 32 + ((q ^ (r0 & 7)) << 2)) * 4;

    int grc[2];
    int aok[2];
    const uint32_t* pB[2];
#pragma unroll
    for (int i = 0; i < 2; ++i) {
        int gr = row0 + r0 + 64 * i;
        aok[i] = (gr < nrows) ? 16 : 0;
        if (gr >= nrows) gr = nrows - 1;
        grc[i] = gr * HDIM + q * 4;
        int c = r0 + 64 * i;
        pB[i] = Bt + (size_t)((c >> 5) * 128 + h0 + (c & 31)) * 256 + q * 4;
    }

    auto stage = [&](int j, int b) {
        const float* Ap = (j < 4) ? A1 : A2;
        const int kcol = (j & 3) * 32;
        const int k0 = j * 32;
        const uint32_t abase = sbase + (b ? S_A1 : S_A0) + sw0;
        const uint32_t bbase = sbase + (b ? S_B1 : S_B0) + sw0;
#pragma unroll
        for (int i = 0; i < 2; ++i) {
            cp_async16(abase + 8192u * i, Ap + grc[i] + kcol, aok[i]);
            cp_async16(bbase + 8192u * i, pB[i] + k0, 16);
        }
        cp_commit();
    };

    const int lane = tid & 31;
    const int warp = tid >> 5;               // 0..15
    const int wm = warp & 3;                 // row quarter
    const int wn = warp >> 2;                // col quarter
    const int g8  = lane >> 2;
    const int tig = lane & 3;

    float acc[2][4][4];
#pragma unroll
    for (int a = 0; a < 2; ++a)
#pragma unroll
        for (int b = 0; b < 4; ++b)
#pragma unroll
            for (int c = 0; c < 4; ++c) acc[a][b][c] = 0.f;

    stage(0, 0);

    for (int j = 0; j < 8; ++j) {
        const int buf = j & 1;
        if (j < 7) { stage(j + 1, buf ^ 1); cp_wait1(); }
        else       { cp_wait0(); }
        __syncthreads();

        const uint32_t* As = Sf + (buf ? S_A1 / 4 : S_A0 / 4);
        const uint32_t* Bs = Sf + (buf ? S_B1 / 4 : S_B0 / 4);

#pragma unroll
        for (int ks = 0; ks < 4; ++ks) {
            uint32_t af[2][4], bf[4][2];
            const int kk = ks * 8 + tig;
#pragma unroll
            for (int mt = 0; mt < 2; ++mt) {
                int r = wm * 32 + mt * 16 + g8;
                af[mt][0] = As[soff(r,     kk)];
                af[mt][1] = As[soff(r + 8, kk)];
                af[mt][2] = As[soff(r,     kk + 4)];
                af[mt][3] = As[soff(r + 8, kk + 4)];
            }
#pragma unroll
            for (int nt = 0; nt < 4; ++nt) {
                int c = wn * 32 + nt * 8 + g8;
                bf[nt][0] = Bs[soff(c, kk)];
                bf[nt][1] = Bs[soff(c, kk + 4)];
            }
#pragma unroll
            for (int mt = 0; mt < 2; ++mt)
#pragma unroll
                for (int nt = 0; nt < 4; ++nt)
                    mma_tf32(acc[mt][nt], af[mt][0], af[mt][1], af[mt][2], af[mt][3],
                             bf[nt][0], bf[nt][1]);
        }
        __syncthreads();
    }

    // ---- park accumulators in smem (Es[128][132]) ----
    float* Es = (float*)smem;
#pragma unroll
    for (int mt = 0; mt < 2; ++mt) {
#pragma unroll
        for (int nt = 0; nt < 4; ++nt) {
            int r = wm * 32 + mt * 16 + g8;
            int c = wn * 32 + nt * 8 + 2 * tig;
            *(float2*)(Es + r * ES_STRIDE + c)       = make_float2(acc[mt][nt][0], acc[mt][nt][1]);
            *(float2*)(Es + (r + 8) * ES_STRIDE + c) = make_float2(acc[mt][nt][2], acc[mt][nt][3]);
        }
    }
    __syncthreads();

    // ---- gate pass: 512 threads -> hh = tid&31, rows (tid>>5) + 16*it ----
    {
        const int hh = tid & 31;
        const int rbase = tid >> 5;
        const int h = h0 + hh;
        const float bi = bW[h]       + bU[h];
        const float bo = bW[128 + h] + bU[128 + h];
        const float bu = bW[256 + h] + bU[256 + h];
        const float bfm = bW[384 + h] + bU[384 + h];
#pragma unroll 4
        for (int it = 0; it < 8; ++it) {
            int r = rbase + it * 16;
            int grow = row0 + r;
            if (grow >= nrows) continue;
            float xi = Es[r * ES_STRIDE + hh]      + bi;
            float xo = Es[r * ES_STRIDE + 32 + hh] + bo;
            float xu = Es[r * ES_STRIDE + 64 + hh] + bu;
            float xf = Es[r * ES_STRIDE + 96 + hh] + bfm;
            float gi = 1.f / (1.f + __expf(-xi));
            float go = 1.f / (1.f + __expf(-xo));
            float gu = tanhf(xu);
            float gf = 1.f / (1.f + __expf(-xf));
            float mcv = mc[(size_t)grow * HDIM + h];
            float cn = gi * gu + gf * mcv;
            float hn = go * tanhf(cn);
            c_out[(size_t)grow * HDIM + h] = cn;
            h_out[(size_t)grow * HDIM + h] = hn;
        }
    }
}

// ---------------- host ----------------
extern "C" void kernel_launch(void* const* d_in, const int* in_sizes, int n_in,
                              void* d_out, int out_size)
{
    const float* x   = (const float*)d_in[0];
    const float* h1  = (const float*)d_in[1];
    const float* c1  = (const float*)d_in[2];
    const float* h2  = (const float*)d_in[3];
    const float* c2  = (const float*)d_in[4];
    const float* W1  = (const float*)d_in[5];
    const float* bW1 = (const float*)d_in[6];
    const float* U1  = (const float*)d_in[7];
    const float* bU1 = (const float*)d_in[8];
    const float* W2  = (const float*)d_in[9];
    const float* bW2 = (const float*)d_in[10];
    const float* U2  = (const float*)d_in[11];
    const float* bU2 = (const float*)d_in[12];
    const int*   src = (const int*)d_in[13];
    const int*   dst = (const int*)d_in[14];

    int n = in_sizes[1] / HDIM;
    int e = in_sizes[13];

    float* out = (float*)d_out;
    float* h1n = out;
    float* c1n = out + (size_t)n * HDIM;
    float* h2n = out + 2 * (size_t)n * HDIM;
    float* c2n = out + 3 * (size_t)n * HDIM;

    static int smem_set = 0;
    if (!smem_set) {
        cudaFuncSetAttribute(lstm_mma_kernel,
                             cudaFuncAttributeMaxDynamicSharedMemorySize, SMEM_TOTAL);
        smem_set = 1;
    }

    {
        dim3 grid(512, 2);
        prep_kernel<<<grid, 256>>>(W1, U1, W2, U2);
    }
    {
        int blocks = (n + 7) / 8;
        gather_kernel<<<blocks, 256>>>(h1, c1, h2, c2, src, dst, n, e);
    }
    int mtiles = (n + 127) / 128;
    dim3 grid(4, mtiles);
    lstm_mma_kernel<<<grid, 512, SMEM_TOTAL>>>(x, bW1, bU1, h1n, c1n, n, 0);
    lstm_mma_kernel<<<grid, 512, SMEM_TOTAL>>>(c1n, bW2, bU2, h2n, c2n, n, 1);
}

// round 8
// speedup vs baseline: 1.3134x; 1.3134x over previous
#include <cuda_runtime.h>
#include <cstdint>
#include <math.h>

#define HDIM 128
#define MAXN 200000

// ---------------- device scratch ----------------
__device__ float g_mh1[MAXN * HDIM];
__device__ float g_mc1[MAXN * HDIM];
__device__ float g_mh2[MAXN * HDIM];
__device__ float g_mc2[MAXN * HDIM];
// transposed + tf32-rounded weights: [phase][n=512][k=256]
__device__ uint32_t g_Bt[2 * 512 * 256];

__device__ __forceinline__ uint32_t smem_u32(const void* p) {
    uint32_t a;
    asm("{ .reg .u64 t; cvta.to.shared.u64 t, %1; cvt.u32.u64 %0, t; }" : "=r"(a) : "l"(p));
    return a;
}
__device__ __forceinline__ uint32_t f2tf32(float f) {
    uint32_t o;
    asm("cvt.rna.tf32.f32 %0, %1;" : "=r"(o) : "f"(f));
    return o;
}
__device__ __forceinline__ void cp_async16(uint32_t dst, const void* src, int src_bytes) {
    asm volatile("cp.async.cg.shared.global [%0], [%1], 16, %2;"
                 :: "r"(dst), "l"(src), "r"(src_bytes) : "memory");
}
__device__ __forceinline__ void cp_commit() {
    asm volatile("cp.async.commit_group;" ::: "memory");
}
__device__ __forceinline__ void cp_wait1() {
    asm volatile("cp.async.wait_group 1;" ::: "memory");
}
__device__ __forceinline__ void cp_wait0() {
    asm volatile("cp.async.wait_group 0;" ::: "memory");
}
__device__ __forceinline__ void mma_tf32(float* d, uint32_t a0, uint32_t a1, uint32_t a2,
                                         uint32_t a3, uint32_t b0, uint32_t b1) {
    asm volatile(
        "mma.sync.aligned.m16n8k8.row.col.f32.tf32.tf32.f32 "
        "{%0,%1,%2,%3}, {%4,%5,%6,%7}, {%8,%9}, {%0,%1,%2,%3};"
        : "+f"(d[0]), "+f"(d[1]), "+f"(d[2]), "+f"(d[3])
        : "r"(a0), "r"(a1), "r"(a2), "r"(a3), "r"(b0), "r"(b1));
}
__device__ __forceinline__ void ldsm_x4(uint32_t& r0, uint32_t& r1, uint32_t& r2, uint32_t& r3,
                                        uint32_t addr) {
    asm volatile("ldmatrix.sync.aligned.m8n8.x4.shared.b16 {%0,%1,%2,%3}, [%4];"
                 : "=r"(r0), "=r"(r1), "=r"(r2), "=r"(r3) : "r"(addr));
}

// ---------------- gather: sorted-dst segment sum, 1 warp / node, 4-edge MLP ----------------
__global__ void gather_kernel(const float* __restrict__ h1, const float* __restrict__ c1,
                              const float* __restrict__ h2, const float* __restrict__ c2,
                              const int* __restrict__ src, const int* __restrict__ dst,
                              int n, int e)
{
    int node = (blockIdx.x * blockDim.x + threadIdx.x) >> 5;
    int lane = threadIdx.x & 31;
    if (node >= n) return;

    int lo = 0, hi = e;
    while (lo < hi) { int mid = (lo + hi) >> 1; if (dst[mid] < node) lo = mid + 1; else hi = mid; }
    int s = lo;
    hi = e;
    while (lo < hi) { int mid = (lo + hi) >> 1; if (dst[mid] < node + 1) lo = mid + 1; else hi = mid; }
    int send = lo;

    float4 a1 = make_float4(0.f, 0.f, 0.f, 0.f);
    float4 a2 = a1, a3 = a1, a4 = a1;
    const int col = lane * 4;

    int idx = s;
    for (; idx + 4 <= send; idx += 4) {
        int b0 = src[idx + 0] * HDIM + col;
        int b1 = src[idx + 1] * HDIM + col;
        int b2 = src[idx + 2] * HDIM + col;
        int b3 = src[idx + 3] * HDIM + col;
        float4 h1a = *(const float4*)(h1 + b0), h1b = *(const float4*)(h1 + b1);
        float4 h1c = *(const float4*)(h1 + b2), h1d = *(const float4*)(h1 + b3);
        float4 c1a = *(const float4*)(c1 + b0), c1b = *(const float4*)(c1 + b1);
        float4 c1c = *(const float4*)(c1 + b2), c1d = *(const float4*)(c1 + b3);
        float4 h2a = *(const float4*)(h2 + b0), h2b = *(const float4*)(h2 + b1);
        float4 h2c = *(const float4*)(h2 + b2), h2d = *(const float4*)(h2 + b3);
        float4 c2a = *(const float4*)(c2 + b0), c2b = *(const float4*)(c2 + b1);
        float4 c2c = *(const float4*)(c2 + b2), c2d = *(const float4*)(c2 + b3);
        a1.x += (h1a.x + h1b.x) + (h1c.x + h1d.x);
        a1.y += (h1a.y + h1b.y) + (h1c.y + h1d.y);
        a1.z += (h1a.z + h1b.z) + (h1c.z + h1d.z);
        a1.w += (h1a.w + h1b.w) + (h1c.w + h1d.w);
        a2.x += (c1a.x + c1b.x) + (c1c.x + c1d.x);
        a2.y += (c1a.y + c1b.y) + (c1c.y + c1d.y);
        a2.z += (c1a.z + c1b.z) + (c1c.z + c1d.z);
        a2.w += (c1a.w + c1b.w) + (c1c.w + c1d.w);
        a3.x += (h2a.x + h2b.x) + (h2c.x + h2d.x);
        a3.y += (h2a.y + h2b.y) + (h2c.y + h2d.y);
        a3.z += (h2a.z + h2b.z) + (h2c.z + h2d.z);
        a3.w += (h2a.w + h2b.w) + (h2c.w + h2d.w);
        a4.x += (c2a.x + c2b.x) + (c2c.x + c2d.x);
        a4.y += (c2a.y + c2b.y) + (c2c.y + c2d.y);
        a4.z += (c2a.z + c2b.z) + (c2c.z + c2d.z);
        a4.w += (c2a.w + c2b.w) + (c2c.w + c2d.w);
    }
    for (; idx < send; ++idx) {
        int b = src[idx] * HDIM + col;
        float4 v;
        v = *(const float4*)(h1 + b); a1.x += v.x; a1.y += v.y; a1.z += v.z; a1.w += v.w;
        v = *(const float4*)(c1 + b); a2.x += v.x; a2.y += v.y; a2.z += v.z; a2.w += v.w;
        v = *(const float4*)(h2 + b); a3.x += v.x; a3.y += v.y; a3.z += v.z; a3.w += v.w;
        v = *(const float4*)(c2 + b); a4.x += v.x; a4.y += v.y; a4.z += v.z; a4.w += v.w;
    }

    int ob = node * HDIM + col;
    *(float4*)(g_mh1 + ob) = a1;
    *(float4*)(g_mc1 + ob) = a2;
    *(float4*)(g_mh2 + ob) = a3;
    *(float4*)(g_mc2 + ob) = a4;
}

// ---------------- prep: weights -> [n=512][k=256] (B^T), tf32-rounded ----------------
__global__ void prep_kernel(const float* __restrict__ W1, const float* __restrict__ U1,
                            const float* __restrict__ W2, const float* __restrict__ U2)
{
    int p = blockIdx.y;
    int i = blockIdx.x * 256 + threadIdx.x;
    int k = i >> 9, n = i & 511;
    const float* W = p ? W2 : W1;
    const float* U = p ? U2 : U1;
    float v = (k < 128) ? W[k * 512 + n] : U[(k - 128) * 512 + n];
    g_Bt[p * 131072 + n * 256 + k] = f2tf32(v);
}

// ---------------- fused HMMA(tf32) GEMM + gates (R4 config + ldmatrix fragments) ----------------
// Tile layout in smem: 128 rows x 32 k-floats, 16B chunk (r, q) at byte r*128 + ((q^(r&7))<<4).
#define S_A0 0
#define S_A1 16384
#define S_B0 32768
#define S_B1 49152
#define ES_STRIDE 132
#define SMEM_TOTAL (128 * ES_STRIDE * 4)   // 67584

__global__ __launch_bounds__(256, 2)
void lstm_mma_kernel(const float* __restrict__ A1,
                     const float* __restrict__ bW, const float* __restrict__ bU,
                     float* __restrict__ h_out, float* __restrict__ c_out,
                     int nrows, int phase)
{
    extern __shared__ char smem[];
    const uint32_t sbase = smem_u32(smem);
    const int tid = threadIdx.x;
    const int h0   = blockIdx.x * 32;
    const int row0 = blockIdx.y * 128;

    const float* A2 = phase ? g_mh2 : g_mh1;
    const float* mc = phase ? g_mc2 : g_mc1;
    const uint32_t* Bt = g_Bt + phase * 131072;

    // ---- staging state (same as R4) ----
    const int r0 = tid >> 3;
    const int q  = tid & 7;
    const uint32_t sw0 = (uint32_t)(r0 * 32 + ((q ^ (r0 & 7)) << 2)) * 4;

    int grc[4];
    int aok[4];
    const uint32_t* pB[4];
#pragma unroll
    for (int i = 0; i < 4; ++i) {
        int gr = row0 + r0 + 32 * i;
        aok[i] = (gr < nrows) ? 16 : 0;
        if (gr >= nrows) gr = nrows - 1;
        grc[i] = gr * HDIM + q * 4;
        pB[i] = Bt + (size_t)(i * 128 + h0 + r0) * 256 + q * 4;
    }

    auto stage = [&](int j, int b) {
        const float* Ap = (j < 4) ? A1 : A2;
        const int kcol = (j & 3) * 32;
        const int k0 = j * 32;
        const uint32_t abase = sbase + (b ? S_A1 : S_A0) + sw0;
        const uint32_t bbase = sbase + (b ? S_B1 : S_B0) + sw0;
#pragma unroll
        for (int i = 0; i < 4; ++i) {
            cp_async16(abase + 4096u * i, Ap + grc[i] + kcol, aok[i]);
            cp_async16(bbase + 4096u * i, pB[i] + k0, 16);
        }
        cp_commit();
    };

    const int lane = tid & 31;
    const int warp = tid >> 5;
    const int wm = warp & 1;          // row half (64 rows)
    const int wn = warp >> 1;         // col quadrant (32 cols)
    const int g8  = lane >> 2;
    const int tig = lane & 3;
    const int lane7 = lane & 7;

    // ldmatrix per-thread invariant address parts (byte offsets within a tile)
    // A x4 (mt): rows wm*64+mt*16 + (lane&15), q = 2ks + (lane>>4)
    const uint32_t a_row_off = (uint32_t)(wm * 64 + (lane & 15)) * 128;
    const int a_qsel = lane >> 4;
    // B x4 (nt pair base 0/2): rows wn*32 + ntb*8 + (lane&7) + ((lane>>4)<<3), q = 2ks + ((lane>>3)&1)
    const uint32_t b_row_off = (uint32_t)(wn * 32 + lane7 + ((lane >> 4) << 3)) * 128;
    const int b_qsel = (lane >> 3) & 1;

    float acc[4][4][4];
#pragma unroll
    for (int a = 0; a < 4; ++a)
#pragma unroll
        for (int b = 0; b < 4; ++b)
#pragma unroll
            for (int c = 0; c < 4; ++c) acc[a][b][c] = 0.f;

    stage(0, 0);

    for (int j = 0; j < 8; ++j) {
        const int buf = j & 1;
        if (j < 7) { stage(j + 1, buf ^ 1); cp_wait1(); }
        else       { cp_wait0(); }
        __syncthreads();

        const uint32_t Abase = sbase + (buf ? S_A1 : S_A0);
        const uint32_t Bbase = sbase + (buf ? S_B1 : S_B0);

#pragma unroll
        for (int ks = 0; ks < 4; ++ks) {
            uint32_t af[4][4], bf[4][2];
            const uint32_t axor = (uint32_t)(((2 * ks + a_qsel) ^ lane7) << 4);
            const uint32_t bxor = (uint32_t)(((2 * ks + b_qsel) ^ lane7) << 4);
#pragma unroll
            for (int mt = 0; mt < 4; ++mt)
                ldsm_x4(af[mt][0], af[mt][1], af[mt][2], af[mt][3],
                        Abase + a_row_off + (uint32_t)mt * 2048 + axor);
            ldsm_x4(bf[0][0], bf[0][1], bf[1][0], bf[1][1], Bbase + b_row_off + bxor);
            ldsm_x4(bf[2][0], bf[2][1], bf[3][0], bf[3][1], Bbase + b_row_off + 2048 + bxor);
#pragma unroll
            for (int mt = 0; mt < 4; ++mt)
#pragma unroll
                for (int nt = 0; nt < 4; ++nt)
                    mma_tf32(acc[mt][nt], af[mt][0], af[mt][1], af[mt][2], af[mt][3],
                             bf[nt][0], bf[nt][1]);
        }
        __syncthreads();
    }

    // ---- park accumulators in smem (Es[128][132]) ----
    float* Es = (float*)smem;
#pragma unroll
    for (int mt = 0; mt < 4; ++mt) {
#pragma unroll
        for (int nt = 0; nt < 4; ++nt) {
            int r = wm * 64 + mt * 16 + g8;
            int c = wn * 32 + nt * 8 + 2 * tig;
            *(float2*)(Es + r * ES_STRIDE + c)       = make_float2(acc[mt][nt][0], acc[mt][nt][1]);
            *(float2*)(Es + (r + 8) * ES_STRIDE + c) = make_float2(acc[mt][nt][2], acc[mt][nt][3]);
        }
    }
    __syncthreads();

    // ---- gate pass ----
    {
        const int hh = tid & 31;
        const int rbase = tid >> 5;
        const int h = h0 + hh;
        const float bi = bW[h]       + bU[h];
        const float bo = bW[128 + h] + bU[128 + h];
        const float bu = bW[256 + h] + bU[256 + h];
        const float bfm = bW[384 + h] + bU[384 + h];
#pragma unroll 4
        for (int it = 0; it < 16; ++it) {
            int r = rbase + it * 8;
            int grow = row0 + r;
            if (grow >= nrows) continue;
            float xi = Es[r * ES_STRIDE + hh]      + bi;
            float xo = Es[r * ES_STRIDE + 32 + hh] + bo;
            float xu = Es[r * ES_STRIDE + 64 + hh] + bu;
            float xf = Es[r * ES_STRIDE + 96 + hh] + bfm;
            float gi = 1.f / (1.f + __expf(-xi));
            float go = 1.f / (1.f + __expf(-xo));
            float gu = tanhf(xu);
            float gf = 1.f / (1.f + __expf(-xf));
            float mcv = mc[(size_t)grow * HDIM + h];
            float cn = gi * gu + gf * mcv;
            float hn = go * tanhf(cn);
            c_out[(size_t)grow * HDIM + h] = cn;
            h_out[(size_t)grow * HDIM + h] = hn;
        }
    }
}

// ---------------- host ----------------
extern "C" void kernel_launch(void* const* d_in, const int* in_sizes, int n_in,
                              void* d_out, int out_size)
{
    const float* x   = (const float*)d_in[0];
    const float* h1  = (const float*)d_in[1];
    const float* c1  = (const float*)d_in[2];
    const float* h2  = (const float*)d_in[3];
    const float* c2  = (const float*)d_in[4];
    const float* W1  = (const float*)d_in[5];
    const float* bW1 = (const float*)d_in[6];
    const float* U1  = (const float*)d_in[7];
    const float* bU1 = (const float*)d_in[8];
    const float* W2  = (const float*)d_in[9];
    const float* bW2 = (const float*)d_in[10];
    const float* U2  = (const float*)d_in[11];
    const float* bU2 = (const float*)d_in[12];
    const int*   src = (const int*)d_in[13];
    const int*   dst = (const int*)d_in[14];

    int n = in_sizes[1] / HDIM;
    int e = in_sizes[13];

    float* out = (float*)d_out;
    float* h1n = out;
    float* c1n = out + (size_t)n * HDIM;
    float* h2n = out + 2 * (size_t)n * HDIM;
    float* c2n = out + 3 * (size_t)n * HDIM;

    static int smem_set = 0;
    if (!smem_set) {
        cudaFuncSetAttribute(lstm_mma_kernel,
                             cudaFuncAttributeMaxDynamicSharedMemorySize, SMEM_TOTAL);
        smem_set = 1;
    }

    {
        dim3 grid(512, 2);
        prep_kernel<<<grid, 256>>>(W1, U1, W2, U2);
    }
    {
        int blocks = (n + 7) / 8;
        gather_kernel<<<blocks, 256>>>(h1, c1, h2, c2, src, dst, n, e);
    }
    int mtiles = (n + 127) / 128;
    dim3 grid(4, mtiles);
    lstm_mma_kernel<<<grid, 256, SMEM_TOTAL>>>(x, bW1, bU1, h1n, c1n, n, 0);
    lstm_mma_kernel<<<grid, 256, SMEM_TOTAL>>>(c1n, bW2, bU2, h2n, c2n, n, 1);
}

// round 9
// speedup vs baseline: 1.4645x; 1.1150x over previous
#include <cuda_runtime.h>
#include <cstdint>
#include <math.h>

#define HDIM 128
#define MAXN 200000

// ---------------- device scratch ----------------
__device__ float g_mh1[MAXN * HDIM];
__device__ float g_mc1[MAXN * HDIM];
__device__ float g_mh2[MAXN * HDIM];
__device__ float g_mc2[MAXN * HDIM];
__device__ int   g_seg[MAXN + 1];
// transposed + tf32-rounded weights: [phase][n=512][k=256]
__device__ uint32_t g_Bt[2 * 512 * 256];

__device__ __forceinline__ uint32_t smem_u32(const void* p) {
    uint32_t a;
    asm("{ .reg .u64 t; cvta.to.shared.u64 t, %1; cvt.u32.u64 %0, t; }" : "=r"(a) : "l"(p));
    return a;
}
__device__ __forceinline__ uint32_t f2tf32(float f) {
    uint32_t o;
    asm("cvt.rna.tf32.f32 %0, %1;" : "=r"(o) : "f"(f));
    return o;
}
__device__ __forceinline__ void cp_async16(uint32_t dst, const void* src, int src_bytes) {
    asm volatile("cp.async.cg.shared.global [%0], [%1], 16, %2;"
                 :: "r"(dst), "l"(src), "r"(src_bytes) : "memory");
}
__device__ __forceinline__ void cp_commit() {
    asm volatile("cp.async.commit_group;" ::: "memory");
}
__device__ __forceinline__ void cp_wait1() {
    asm volatile("cp.async.wait_group 1;" ::: "memory");
}
__device__ __forceinline__ void cp_wait0() {
    asm volatile("cp.async.wait_group 0;" ::: "memory");
}
__device__ __forceinline__ void mma_tf32(float* d, uint32_t a0, uint32_t a1, uint32_t a2,
                                         uint32_t a3, uint32_t b0, uint32_t b1) {
    asm volatile(
        "mma.sync.aligned.m16n8k8.row.col.f32.tf32.tf32.f32 "
        "{%0,%1,%2,%3}, {%4,%5,%6,%7}, {%8,%9}, {%0,%1,%2,%3};"
        : "+f"(d[0]), "+f"(d[1]), "+f"(d[2]), "+f"(d[3])
        : "r"(a0), "r"(a1), "r"(a2), "r"(a3), "r"(b0), "r"(b1));
}
__device__ __forceinline__ void ldsm_x4(uint32_t& r0, uint32_t& r1, uint32_t& r2, uint32_t& r3,
                                        uint32_t addr) {
    asm volatile("ldmatrix.sync.aligned.m8n8.x4.shared.b16 {%0,%1,%2,%3}, [%4];"
                 : "=r"(r0), "=r"(r1), "=r"(r2), "=r"(r3) : "r"(addr));
}

// ---------------- seg: boundaries of sorted dst -> g_seg[0..n] ----------------
__global__ void seg_kernel(const int* __restrict__ dst, int n, int e)
{
    int i = blockIdx.x * blockDim.x + threadIdx.x;
    if (i > e) return;
    int lo = (i == 0) ? 0 : dst[i - 1] + 1;
    int hi = (i == e) ? n : dst[i];
    for (int v = lo; v <= hi; ++v) g_seg[v] = i;
}

// ---------------- gather: segment sum via precomputed boundaries ----------------
__global__ void gather_kernel(const float* __restrict__ h1, const float* __restrict__ c1,
                              const float* __restrict__ h2, const float* __restrict__ c2,
                              const int* __restrict__ src, int n)
{
    int node = (blockIdx.x * blockDim.x + threadIdx.x) >> 5;
    int lane = threadIdx.x & 31;
    if (node >= n) return;

    int s    = g_seg[node];
    int send = g_seg[node + 1];

    float4 a1 = make_float4(0.f, 0.f, 0.f, 0.f);
    float4 a2 = a1, a3 = a1, a4 = a1;
    const int col = lane * 4;

    int idx = s;
    for (; idx + 4 <= send; idx += 4) {
        int b0 = src[idx + 0] * HDIM + col;
        int b1 = src[idx + 1] * HDIM + col;
        int b2 = src[idx + 2] * HDIM + col;
        int b3 = src[idx + 3] * HDIM + col;
        float4 h1a = *(const float4*)(h1 + b0), h1b = *(const float4*)(h1 + b1);
        float4 h1c = *(const float4*)(h1 + b2), h1d = *(const float4*)(h1 + b3);
        float4 c1a = *(const float4*)(c1 + b0), c1b = *(const float4*)(c1 + b1);
        float4 c1c = *(const float4*)(c1 + b2), c1d = *(const float4*)(c1 + b3);
        float4 h2a = *(const float4*)(h2 + b0), h2b = *(const float4*)(h2 + b1);
        float4 h2c = *(const float4*)(h2 + b2), h2d = *(const float4*)(h2 + b3);
        float4 c2a = *(const float4*)(c2 + b0), c2b = *(const float4*)(c2 + b1);
        float4 c2c = *(const float4*)(c2 + b2), c2d = *(const float4*)(c2 + b3);
        a1.x += (h1a.x + h1b.x) + (h1c.x + h1d.x);
        a1.y += (h1a.y + h1b.y) + (h1c.y + h1d.y);
        a1.z += (h1a.z + h1b.z) + (h1c.z + h1d.z);
        a1.w += (h1a.w + h1b.w) + (h1c.w + h1d.w);
        a2.x += (c1a.x + c1b.x) + (c1c.x + c1d.x);
        a2.y += (c1a.y + c1b.y) + (c1c.y + c1d.y);
        a2.z += (c1a.z + c1b.z) + (c1c.z + c1d.z);
        a2.w += (c1a.w + c1b.w) + (c1c.w + c1d.w);
        a3.x += (h2a.x + h2b.x) + (h2c.x + h2d.x);
        a3.y += (h2a.y + h2b.y) + (h2c.y + h2d.y);
        a3.z += (h2a.z + h2b.z) + (h2c.z + h2d.z);
        a3.w += (h2a.w + h2b.w) + (h2c.w + h2d.w);
        a4.x += (c2a.x + c2b.x) + (c2c.x + c2d.x);
        a4.y += (c2a.y + c2b.y) + (c2c.y + c2d.y);
        a4.z += (c2a.z + c2b.z) + (c2c.z + c2d.z);
        a4.w += (c2a.w + c2b.w) + (c2c.w + c2d.w);
    }
    for (; idx < send; ++idx) {
        int b = src[idx] * HDIM + col;
        float4 v;
        v = *(const float4*)(h1 + b); a1.x += v.x; a1.y += v.y; a1.z += v.z; a1.w += v.w;
        v = *(const float4*)(c1 + b); a2.x += v.x; a2.y += v.y; a2.z += v.z; a2.w += v.w;
        v = *(const float4*)(h2 + b); a3.x += v.x; a3.y += v.y; a3.z += v.z; a3.w += v.w;
        v = *(const float4*)(c2 + b); a4.x += v.x; a4.y += v.y; a4.z += v.z; a4.w += v.w;
    }

    int ob = node * HDIM + col;
    *(float4*)(g_mh1 + ob) = a1;
    *(float4*)(g_mc1 + ob) = a2;
    *(float4*)(g_mh2 + ob) = a3;
    *(float4*)(g_mc2 + ob) = a4;
}

// ---------------- prep: weights -> [n=512][k=256] (B^T), tf32-rounded ----------------
__global__ void prep_kernel(const float* __restrict__ W1, const float* __restrict__ U1,
                            const float* __restrict__ W2, const float* __restrict__ U2)
{
    int p = blockIdx.y;
    int i = blockIdx.x * 256 + threadIdx.x;
    int k = i >> 9, n = i & 511;
    const float* W = p ? W2 : W1;
    const float* U = p ? U2 : U1;
    float v = (k < 128) ? W[k * 512 + n] : U[(k - 128) * 512 + n];
    g_Bt[p * 131072 + n * 256 + k] = f2tf32(v);
}

// ---------------- fused HMMA(tf32) GEMM + gates ----------------
// R8 fragment path (ldmatrix) + 3-stage cp.async ring, ONE sync per chunk.
// Stage slot: A at +0, B at +16384, slot stride 32768, 3 slots = 96KB.
#define SLOT 32768
#define ES_STRIDE 132
#define SMEM_TOTAL (3 * SLOT)   // 98304 >= 128*132*4

__global__ __launch_bounds__(256, 2)
void lstm_mma_kernel(const float* __restrict__ A1,
                     const float* __restrict__ bW, const float* __restrict__ bU,
                     float* __restrict__ h_out, float* __restrict__ c_out,
                     int nrows, int phase)
{
    extern __shared__ char smem[];
    const uint32_t sbase = smem_u32(smem);
    const int tid = threadIdx.x;
    const int h0   = blockIdx.x * 32;
    const int row0 = blockIdx.y * 128;

    const float* A2 = phase ? g_mh2 : g_mh1;
    const float* mc = phase ? g_mc2 : g_mc1;
    const uint32_t* Bt = g_Bt + phase * 131072;

    // ---- staging state ----
    const int r0 = tid >> 3;
    const int q  = tid & 7;
    const uint32_t sw0 = (uint32_t)(r0 * 32 + ((q ^ (r0 & 7)) << 2)) * 4;

    int grc[4];
    int aok[4];
    const uint32_t* pB[4];
#pragma unroll
    for (int i = 0; i < 4; ++i) {
        int gr = row0 + r0 + 32 * i;
        aok[i] = (gr < nrows) ? 16 : 0;
        if (gr >= nrows) gr = nrows - 1;
        grc[i] = gr * HDIM + q * 4;
        pB[i] = Bt + (size_t)(i * 128 + h0 + r0) * 256 + q * 4;
    }

    auto stage = [&](int j, uint32_t slotbase) {
        const float* Ap = (j < 4) ? A1 : A2;
        const int kcol = (j & 3) * 32;
        const int k0 = j * 32;
        const uint32_t abase = slotbase + sw0;
        const uint32_t bbase = slotbase + 16384u + sw0;
#pragma unroll
        for (int i = 0; i < 4; ++i) {
            cp_async16(abase + 4096u * i, Ap + grc[i] + kcol, aok[i]);
            cp_async16(bbase + 4096u * i, pB[i] + k0, 16);
        }
        cp_commit();
    };

    const int lane = tid & 31;
    const int warp = tid >> 5;
    const int wm = warp & 1;
    const int wn = warp >> 1;
    const int g8  = lane >> 2;
    const int tig = lane & 3;
    const int lane7 = lane & 7;

    const uint32_t a_row_off = (uint32_t)(wm * 64 + (lane & 15)) * 128;
    const int a_qsel = lane >> 4;
    const uint32_t b_row_off = (uint32_t)(wn * 32 + lane7 + ((lane >> 4) << 3)) * 128;
    const int b_qsel = (lane >> 3) & 1;

    float acc[4][4][4];
#pragma unroll
    for (int a = 0; a < 4; ++a)
#pragma unroll
        for (int b = 0; b < 4; ++b)
#pragma unroll
            for (int c = 0; c < 4; ++c) acc[a][b][c] = 0.f;

    // 3-slot ring: compute from s0, stage j+2 into s2, rotate.
    uint32_t s0 = sbase, s1 = sbase + SLOT, s2 = sbase + 2 * SLOT;
    stage(0, s0);
    stage(1, s1);

#pragma unroll 1
    for (int j = 0; j < 8; ++j) {
        if (j == 7) cp_wait0(); else cp_wait1();
        __syncthreads();              // all warps done reading slot that j+2 will overwrite

        if (j + 2 < 8) stage(j + 2, s2);

        const uint32_t Abase = s0;
        const uint32_t Bbase = s0 + 16384u;

#pragma unroll
        for (int ks = 0; ks < 4; ++ks) {
            uint32_t af[4][4], bf[4][2];
            const uint32_t axor = (uint32_t)(((2 * ks + a_qsel) ^ lane7) << 4);
            const uint32_t bxor = (uint32_t)(((2 * ks + b_qsel) ^ lane7) << 4);
#pragma unroll
            for (int mt = 0; mt < 4; ++mt)
                ldsm_x4(af[mt][0], af[mt][1], af[mt][2], af[mt][3],
                        Abase + a_row_off + (uint32_t)mt * 2048 + axor);
            ldsm_x4(bf[0][0], bf[0][1], bf[1][0], bf[1][1], Bbase + b_row_off + bxor);
            ldsm_x4(bf[2][0], bf[2][1], bf[3][0], bf[3][1], Bbase + b_row_off + 2048 + bxor);
#pragma unroll
            for (int mt = 0; mt < 4; ++mt)
#pragma unroll
                for (int nt = 0; nt < 4; ++nt)
                    mma_tf32(acc[mt][nt], af[mt][0], af[mt][1], af[mt][2], af[mt][3],
                             bf[nt][0], bf[nt][1]);
        }
        uint32_t t = s0; s0 = s1; s1 = s2; s2 = t;
    }

    __syncthreads();   // compute done before Es overwrites stage buffers

    // ---- park accumulators in smem (Es[128][132]) ----
    float* Es = (float*)smem;
#pragma unroll
    for (int mt = 0; mt < 4; ++mt) {
#pragma unroll
        for (int nt = 0; nt < 4; ++nt) {
            int r = wm * 64 + mt * 16 + g8;
            int c = wn * 32 + nt * 8 + 2 * tig;
            *(float2*)(Es + r * ES_STRIDE + c)       = make_float2(acc[mt][nt][0], acc[mt][nt][1]);
            *(float2*)(Es + (r + 8) * ES_STRIDE + c) = make_float2(acc[mt][nt][2], acc[mt][nt][3]);
        }
    }
    __syncthreads();

    // ---- gate pass ----
    {
        const int hh = tid & 31;
        const int rbase = tid >> 5;
        const int h = h0 + hh;
        const float bi = bW[h]       + bU[h];
        const float bo = bW[128 + h] + bU[128 + h];
        const float bu = bW[256 + h] + bU[256 + h];
        const float bfm = bW[384 + h] + bU[384 + h];
#pragma unroll 4
        for (int it = 0; it < 16; ++it) {
            int r = rbase + it * 8;
            int grow = row0 + r;
            if (grow >= nrows) continue;
            float xi = Es[r * ES_STRIDE + hh]      + bi;
            float xo = Es[r * ES_STRIDE + 32 + hh] + bo;
            float xu = Es[r * ES_STRIDE + 64 + hh] + bu;
            float xf = Es[r * ES_STRIDE + 96 + hh] + bfm;
            float gi = 1.f / (1.f + __expf(-xi));
            float go = 1.f / (1.f + __expf(-xo));
            float gu = tanhf(xu);
            float gf = 1.f / (1.f + __expf(-xf));
            float mcv = mc[(size_t)grow * HDIM + h];
            float cn = gi * gu + gf * mcv;
            float hn = go * tanhf(cn);
            c_out[(size_t)grow * HDIM + h] = cn;
            h_out[(size_t)grow * HDIM + h] = hn;
        }
    }
}

// ---------------- host ----------------
extern "C" void kernel_launch(void* const* d_in, const int* in_sizes, int n_in,
                              void* d_out, int out_size)
{
    const float* x   = (const float*)d_in[0];
    const float* h1  = (const float*)d_in[1];
    const float* c1  = (const float*)d_in[2];
    const float* h2  = (const float*)d_in[3];
    const float* c2  = (const float*)d_in[4];
    const float* W1  = (const float*)d_in[5];
    const float* bW1 = (const float*)d_in[6];
    const float* U1  = (const float*)d_in[7];
    const float* bU1 = (const float*)d_in[8];
    const float* W2  = (const float*)d_in[9];
    const float* bW2 = (const float*)d_in[10];
    const float* U2  = (const float*)d_in[11];
    const float* bU2 = (const float*)d_in[12];
    const int*   src = (const int*)d_in[13];
    const int*   dst = (const int*)d_in[14];

    int n = in_sizes[1] / HDIM;
    int e = in_sizes[13];

    float* out = (float*)d_out;
    float* h1n = out;
    float* c1n = out + (size_t)n * HDIM;
    float* h2n = out + 2 * (size_t)n * HDIM;
    float* c2n = out + 3 * (size_t)n * HDIM;

    static int smem_set = 0;
    if (!smem_set) {
        cudaFuncSetAttribute(lstm_mma_kernel,
                             cudaFuncAttributeMaxDynamicSharedMemorySize, SMEM_TOTAL);
        smem_set = 1;
    }

    {
        dim3 grid(512, 2);
        prep_kernel<<<grid, 256>>>(W1, U1, W2, U2);
    }
    seg_kernel<<<(e + 256) / 256, 256>>>(dst, n, e);
    {
        int blocks = (n + 7) / 8;
        gather_kernel<<<blocks, 256>>>(h1, c1, h2, c2, src, n);
    }
    int mtiles = (n + 127) / 128;
    dim3 grid(4, mtiles);
    lstm_mma_kernel<<<grid, 256, SMEM_TOTAL>>>(x, bW1, bU1, h1n, c1n, n, 0);
    lstm_mma_kernel<<<grid, 256, SMEM_TOTAL>>>(c1n, bW2, bU2, h2n, c2n, n, 1);
}